// round 2
// baseline (speedup 1.0000x reference)
#include <cuda_runtime.h>

// ---------------- problem constants ----------------
#define BATCH 64
#define C576  576
#define H7    7
#define HW49  49
#define NEDGE 24

// ---------------- scratch (device globals; no allocation) ----------------
__device__ float g_bufA[BATCH*C576*HW49];
__device__ float g_bufB[BATCH*C576*HW49];
__device__ float g_first[BATCH*C576*HW49];
__device__ float g_second[BATCH*C576*HW49];
__device__ float g_msgs[NEDGE*BATCH*64*HW49];
__device__ float g_head[BATCH*C576*196];

__constant__ int c_esrc[NEDGE] = {1,3, 0,2,4, 1,5, 0,4,6, 1,3,5,7, 2,4,8, 3,7, 4,6,8, 5,7};
__constant__ int c_doff[10]    = {0,2,5,7,10,14,17,19,22,24};

// =====================================================================
// conv0: 3x3 stride2 pad1, 256->576, 14x14 -> 7x7, fused GN(36)+ReLU
// grid (9 oc-tiles, 64 b), block 128 (112 active)
// =====================================================================
__global__ __launch_bounds__(128) void conv0_kernel(
    const float* __restrict__ x, const float* __restrict__ w,
    const float* __restrict__ bias, const float* __restrict__ gamma,
    const float* __restrict__ beta, float* __restrict__ dst)
{
    const int b   = blockIdx.y;
    const int ocb = blockIdx.x * 64;
    __shared__ float in_s[8][16][16];
    __shared__ float w_s[8][64][9];
    __shared__ float psum[128], psum2[128];
    __shared__ float gmean[4], ginv[4];
    const int tid = threadIdx.x;
    const bool active = tid < 112;
    const int row = tid % 7;
    const int og  = tid / 7;

    float acc[4][7];
    if (active) {
#pragma unroll
        for (int oi = 0; oi < 4; oi++) {
            float bv = bias[ocb + og*4 + oi];
#pragma unroll
            for (int xo = 0; xo < 7; xo++) acc[oi][xo] = bv;
        }
    }

    for (int ic0 = 0; ic0 < 256; ic0 += 8) {
        for (int li = tid; li < 8*64*9; li += 128) {
            int ocl = li / 72; int rem = li % 72; int icl = rem / 9; int tap = rem % 9;
            w_s[icl][ocl][tap] = w[((ocb + ocl)*256 + ic0 + icl)*9 + tap];
        }
        for (int li = tid; li < 8*256; li += 128) {
            int icl = li >> 8; int rem = li & 255; int yy = rem >> 4; int xx = rem & 15;
            float v = 0.f;
            if (yy >= 1 && yy <= 14 && xx >= 1 && xx <= 14)
                v = x[((b*256 + ic0 + icl)*14 + yy - 1)*14 + xx - 1];
            in_s[icl][yy][xx] = v;
        }
        __syncthreads();
        if (active) {
#pragma unroll 1
            for (int ic = 0; ic < 8; ic++) {
#pragma unroll
                for (int dy = 0; dy < 3; dy++) {
                    float v[15];
#pragma unroll
                    for (int k = 0; k < 15; k++) v[k] = in_s[ic][2*row + dy][k];
#pragma unroll
                    for (int oi = 0; oi < 4; oi++) {
                        float w0 = w_s[ic][og*4 + oi][dy*3 + 0];
                        float w1 = w_s[ic][og*4 + oi][dy*3 + 1];
                        float w2 = w_s[ic][og*4 + oi][dy*3 + 2];
#pragma unroll
                        for (int xo = 0; xo < 7; xo++)
                            acc[oi][xo] = fmaf(w0, v[2*xo],
                                          fmaf(w1, v[2*xo+1],
                                          fmaf(w2, v[2*xo+2], acc[oi][xo])));
                    }
                }
            }
        }
        __syncthreads();
    }

    // GN epilogue (4 complete groups of 16ch per block)
    float s = 0.f, s2 = 0.f;
    if (active) {
#pragma unroll
        for (int oi = 0; oi < 4; oi++)
#pragma unroll
            for (int xo = 0; xo < 7; xo++) { float t = acc[oi][xo]; s += t; s2 += t*t; }
    }
    psum[tid] = s; psum2[tid] = s2;
    __syncthreads();
    if (active && (tid % 28) == 0) {
        float a = 0.f, a2 = 0.f;
        for (int i = 0; i < 28; i++) { a += psum[tid + i]; a2 += psum2[tid + i]; }
        float m   = a  * (1.f/784.f);
        float var = a2 * (1.f/784.f) - m*m;
        gmean[tid/28] = m;
        ginv[tid/28]  = rsqrtf(var + 1e-5f);
    }
    __syncthreads();
    if (active) {
        int gi = og >> 2;
        float m = gmean[gi], inv = ginv[gi];
#pragma unroll
        for (int oi = 0; oi < 4; oi++) {
            int ch = ocb + og*4 + oi;
            float ga = gamma[ch], be = beta[ch];
#pragma unroll
            for (int xo = 0; xo < 7; xo++) {
                float vv = (acc[oi][xo] - m) * inv * ga + be;
                dst[((b*C576 + ch)*7 + row)*7 + xo] = fmaxf(vv, 0.f);
            }
        }
    }
}

// =====================================================================
// conv1: 3x3 stride1 pad1, 576->576 on 7x7, fused GN(36)+ReLU
// grid (9, 64), block 128 (112 active)
// =====================================================================
__global__ __launch_bounds__(128) void conv1_kernel(
    const float* __restrict__ src, const float* __restrict__ w,
    const float* __restrict__ bias, const float* __restrict__ gamma,
    const float* __restrict__ beta, float* __restrict__ dst)
{
    const int b   = blockIdx.y;
    const int ocb = blockIdx.x * 64;
    __shared__ float in_s[16][9][9];
    __shared__ float w_s[16][64][9];
    __shared__ float psum[128], psum2[128];
    __shared__ float gmean[4], ginv[4];
    const int tid = threadIdx.x;
    const bool active = tid < 112;
    const int row = tid % 7;
    const int og  = tid / 7;

    float acc[4][7];
    if (active) {
#pragma unroll
        for (int oi = 0; oi < 4; oi++) {
            float bv = bias[ocb + og*4 + oi];
#pragma unroll
            for (int xo = 0; xo < 7; xo++) acc[oi][xo] = bv;
        }
    }

    for (int ic0 = 0; ic0 < 576; ic0 += 16) {
        for (int li = tid; li < 16*64*9; li += 128) {
            int ocl = li / 144; int rem = li % 144; int icl = rem / 9; int tap = rem % 9;
            w_s[icl][ocl][tap] = w[((ocb + ocl)*576 + ic0 + icl)*9 + tap];
        }
        for (int li = tid; li < 16*81; li += 128) {
            int icl = li / 81; int rem = li % 81; int yy = rem / 9; int xx = rem % 9;
            float v = 0.f;
            if (yy >= 1 && yy <= 7 && xx >= 1 && xx <= 7)
                v = src[((b*C576 + ic0 + icl)*7 + yy - 1)*7 + xx - 1];
            in_s[icl][yy][xx] = v;
        }
        __syncthreads();
        if (active) {
#pragma unroll 1
            for (int ic = 0; ic < 16; ic++) {
#pragma unroll
                for (int dy = 0; dy < 3; dy++) {
                    float v[9];
#pragma unroll
                    for (int k = 0; k < 9; k++) v[k] = in_s[ic][row + dy][k];
#pragma unroll
                    for (int oi = 0; oi < 4; oi++) {
                        float w0 = w_s[ic][og*4 + oi][dy*3 + 0];
                        float w1 = w_s[ic][og*4 + oi][dy*3 + 1];
                        float w2 = w_s[ic][og*4 + oi][dy*3 + 2];
#pragma unroll
                        for (int xo = 0; xo < 7; xo++)
                            acc[oi][xo] = fmaf(w0, v[xo],
                                          fmaf(w1, v[xo+1],
                                          fmaf(w2, v[xo+2], acc[oi][xo])));
                    }
                }
            }
        }
        __syncthreads();
    }

    float s = 0.f, s2 = 0.f;
    if (active) {
#pragma unroll
        for (int oi = 0; oi < 4; oi++)
#pragma unroll
            for (int xo = 0; xo < 7; xo++) { float t = acc[oi][xo]; s += t; s2 += t*t; }
    }
    psum[tid] = s; psum2[tid] = s2;
    __syncthreads();
    if (active && (tid % 28) == 0) {
        float a = 0.f, a2 = 0.f;
        for (int i = 0; i < 28; i++) { a += psum[tid + i]; a2 += psum2[tid + i]; }
        float m   = a  * (1.f/784.f);
        float var = a2 * (1.f/784.f) - m*m;
        gmean[tid/28] = m;
        ginv[tid/28]  = rsqrtf(var + 1e-5f);
    }
    __syncthreads();
    if (active) {
        int gi = og >> 2;
        float m = gmean[gi], inv = ginv[gi];
#pragma unroll
        for (int oi = 0; oi < 4; oi++) {
            int ch = ocb + og*4 + oi;
            float ga = gamma[ch], be = beta[ch];
#pragma unroll
            for (int xo = 0; xo < 7; xo++) {
                float vv = (acc[oi][xo] - m) * inv * ga + be;
                dst[((b*C576 + ch)*7 + row)*7 + xo] = fmaxf(vv, 0.f);
            }
        }
    }
}

// =====================================================================
// message passing: per-edge depthwise 5x5 (pad2) + pointwise 64x64
// grid (24 edges, 64 b), block 256. Writes msgs[e][b][o][49].
// =====================================================================
__global__ __launch_bounds__(256) void mp_kernel(
    const float* __restrict__ src, const float* __restrict__ dw_w,
    const float* __restrict__ dw_b, const float* __restrict__ pw_w,
    const float* __restrict__ pw_b, float* __restrict__ msgs)
{
    const int e = blockIdx.x, b = blockIdx.y;
    const int sg = c_esrc[e];
    __shared__ float in_pad[64][11][11];
    __shared__ float t_s[64][49];
    const int tid = threadIdx.x;

    for (int li = tid; li < 64*121; li += 256) {
        int c = li / 121; int rem = li % 121; int yy = rem / 11; int xx = rem % 11;
        float v = 0.f;
        if (yy >= 2 && yy <= 8 && xx >= 2 && xx <= 8)
            v = src[((b*C576 + sg*64 + c)*7 + yy - 2)*7 + xx - 2];
        in_pad[c][yy][xx] = v;
    }
    __syncthreads();

    for (int idx = tid; idx < 64*49; idx += 256) {
        int c = idx / 49, p = idx % 49, y = p / 7, xx = p % 7;
        float acc = dw_b[e*64 + c];
        const float* wp = dw_w + (e*64 + c)*25;
#pragma unroll
        for (int ky = 0; ky < 5; ky++)
#pragma unroll
            for (int kx = 0; kx < 5; kx++)
                acc = fmaf(in_pad[c][y + ky][xx + kx], wp[ky*5 + kx], acc);
        t_s[c][p] = acc;
    }
    __syncthreads();

    for (int idx = tid; idx < 64*49; idx += 256) {
        int o = idx / 49, p = idx % 49;
        float acc = pw_b[e*64 + o];
        const float* wp = pw_w + (e*64 + o)*64;
#pragma unroll 8
        for (int c = 0; c < 64; c++)
            acc = fmaf(wp[c], t_s[c][p], acc);
        msgs[((e*BATCH + b)*64 + o)*49 + p] = acc;
    }
}

// =====================================================================
// segment-sum gather: out = base + sum(incoming msgs). Deterministic.
// =====================================================================
__global__ __launch_bounds__(256) void gather_kernel(
    const float* __restrict__ base, const float* __restrict__ msgs,
    float* __restrict__ out)
{
    int i = blockIdx.x * blockDim.x + threadIdx.x;
    if (i >= BATCH*C576*HW49) return;
    int b = i / (C576*HW49); int rem = i % (C576*HW49);
    int ch = rem / 49; int p = rem % 49;
    int g = ch >> 6; int o = ch & 63;
    float v = base[i];
    int e1 = c_doff[g + 1];
    for (int e = c_doff[g]; e < e1; e++)
        v += msgs[((e*BATCH + b)*64 + o)*49 + p];
    out[i] = v;
}

// =====================================================================
// deconv1 (ConvTranspose k4 s2 p1, groups=9, 64->64 per group, 7->14)
// fused GN(9 groups = whole block) + ReLU.
// grid (9 g, 64 b), block 256 (224 active: 16 oc-groups x 14 rows)
// =====================================================================
__global__ __launch_bounds__(256) void deconv1_kernel(
    const float* __restrict__ src, const float* __restrict__ w,
    const float* __restrict__ bias, const float* __restrict__ gamma,
    const float* __restrict__ beta, float* __restrict__ dst)
{
    const int g = blockIdx.x, b = blockIdx.y;
    __shared__ float in_s[64*49];
    __shared__ float red[256], red2[256];
    __shared__ float s_stats[2];
    const int tid = threadIdx.x;

    for (int li = tid; li < 64*49; li += 256)
        in_s[li] = src[(b*C576 + g*64)*49 + li];
    __syncthreads();

    const bool active = tid < 224;
    const int ocg = tid / 14;  // 0..15
    const int row = tid % 14;  // oy
    float acc[4][14];
    if (active) {
#pragma unroll
        for (int oi = 0; oi < 4; oi++)
#pragma unroll
            for (int ox = 0; ox < 14; ox++) acc[oi][ox] = 0.f;

        const int kp = (row + 1) & 1;  // ky parity
#pragma unroll 1
        for (int ic = 0; ic < 64; ic++) {
            const float* wbase = w + (((g*64 + ic)*64) + ocg*4) * 16;
#pragma unroll
            for (int t = 0; t < 2; t++) {
                int ky = kp + 2*t;
                int iy = (row + 1 - ky) >> 1;
                if (iy < 0 || iy >= 7) continue;
                float v[7];
#pragma unroll
                for (int j = 0; j < 7; j++) v[j] = in_s[ic*49 + iy*7 + j];
#pragma unroll
                for (int kx = 0; kx < 4; kx++) {
                    float w4[4];
#pragma unroll
                    for (int oi = 0; oi < 4; oi++)
                        w4[oi] = __ldg(wbase + oi*16 + ky*4 + kx);
#pragma unroll
                    for (int j = 0; j < 7; j++) {
                        const int ox = 2*j - 1 + kx;
                        if (ox < 0 || ox > 13) continue;  // compile-time
#pragma unroll
                        for (int oi = 0; oi < 4; oi++)
                            acc[oi][ox] = fmaf(w4[oi], v[j], acc[oi][ox]);
                    }
                }
            }
        }
    }

    float lsum = 0.f, lsum2 = 0.f;
    if (active) {
#pragma unroll
        for (int oi = 0; oi < 4; oi++) {
            float bv = bias[g*64 + ocg*4 + oi];
#pragma unroll
            for (int ox = 0; ox < 14; ox++) {
                float val = acc[oi][ox] + bv;
                acc[oi][ox] = val;
                lsum += val; lsum2 += val*val;
            }
        }
    }
    red[tid] = lsum; red2[tid] = lsum2;
    __syncthreads();
    for (int s = 128; s > 0; s >>= 1) {
        if (tid < s) { red[tid] += red[tid + s]; red2[tid] += red2[tid + s]; }
        __syncthreads();
    }
    if (tid == 0) {
        float m   = red[0]  * (1.f/12544.f);
        float var = red2[0] * (1.f/12544.f) - m*m;
        s_stats[0] = m;
        s_stats[1] = rsqrtf(var + 1e-5f);
    }
    __syncthreads();
    if (active) {
        float m = s_stats[0], inv = s_stats[1];
#pragma unroll
        for (int oi = 0; oi < 4; oi++) {
            int ch = g*64 + ocg*4 + oi;
            float ga = gamma[ch], be = beta[ch];
#pragma unroll
            for (int ox = 0; ox < 14; ox++) {
                float val = (acc[oi][ox] - m) * inv * ga + be;
                dst[(b*C576 + ch)*196 + row*14 + ox] = fmaxf(val, 0.f);
            }
        }
    }
}

// =====================================================================
// up2 (ConvTranspose k4 s2 p1, groups=9, 64->1 per group, 14->28)
// grid (9 g, 64 b), block 64 (49 active: each thread a 4x4 output tile)
// =====================================================================
__global__ __launch_bounds__(64) void up2_kernel(
    const float* __restrict__ src, const float* __restrict__ w,
    const float* __restrict__ bias, float* __restrict__ out)
{
    const int g = blockIdx.x, b = blockIdx.y;
    const int tid = threadIdx.x;
    if (tid >= 49) return;
    const int r2 = tid / 7, c2 = tid % 7;
    const int iy0 = 2*r2 - 1, ix0 = 2*c2 - 1;

    // for output row/col offset d (0..3): the 2 (k, rel-input) pairs
    const int TK[4][2] = {{1,3},{0,2},{1,3},{0,2}};
    const int TR[4][2] = {{1,0},{2,1},{2,1},{3,2}};

    float acc[4][4];
#pragma unroll
    for (int a = 0; a < 4; a++)
#pragma unroll
        for (int c = 0; c < 4; c++) acc[a][c] = 0.f;

#pragma unroll 1
    for (int ic = 0; ic < 64; ic++) {
        const float* ib = src + (b*C576 + g*64 + ic)*196;
        float vin[4][4];
#pragma unroll
        for (int a = 0; a < 4; a++) {
            int iy = iy0 + a;
#pragma unroll
            for (int c = 0; c < 4; c++) {
                int ix = ix0 + c;
                vin[a][c] = (iy >= 0 && iy < 14 && ix >= 0 && ix < 14)
                          ? __ldg(ib + iy*14 + ix) : 0.f;
            }
        }
        float w16[16];
#pragma unroll
        for (int t = 0; t < 16; t++) w16[t] = __ldg(w + (g*64 + ic)*16 + t);

#pragma unroll
        for (int dy = 0; dy < 4; dy++)
#pragma unroll
            for (int dx = 0; dx < 4; dx++)
#pragma unroll
                for (int i = 0; i < 2; i++)
#pragma unroll
                    for (int j = 0; j < 2; j++)
                        acc[dy][dx] = fmaf(w16[TK[dy][i]*4 + TK[dx][j]],
                                           vin[TR[dy][i]][TR[dx][j]], acc[dy][dx]);
    }
    const float bz = bias[g];
#pragma unroll
    for (int dy = 0; dy < 4; dy++)
#pragma unroll
        for (int dx = 0; dx < 4; dx++)
            out[(b*9 + g)*784 + (4*r2 + dy)*28 + (4*c2 + dx)] = acc[dy][dx] + bz;
}

// =====================================================================
// host launch
// =====================================================================
extern "C" void kernel_launch(void* const* d_in, const int* in_sizes, int n_in,
                              void* d_out, int out_size)
{
    const float* x        = (const float*)d_in[0];
    const float* convs_w0 = (const float*)d_in[1];
    const float* convs_b0 = (const float*)d_in[2];
    const float* convs_w  = (const float*)d_in[3];
    const float* convs_b  = (const float*)d_in[4];
    const float* gn_gamma = (const float*)d_in[5];
    const float* gn_beta  = (const float*)d_in[6];
    const float* fo_dw_w  = (const float*)d_in[7];
    const float* fo_dw_b  = (const float*)d_in[8];
    const float* fo_pw_w  = (const float*)d_in[9];
    const float* fo_pw_b  = (const float*)d_in[10];
    const float* so_dw_w  = (const float*)d_in[11];
    const float* so_dw_b  = (const float*)d_in[12];
    const float* so_pw_w  = (const float*)d_in[13];
    const float* so_pw_b  = (const float*)d_in[14];
    const float* up1_w    = (const float*)d_in[15];
    const float* up1_b    = (const float*)d_in[16];
    const float* sbn1_g   = (const float*)d_in[17];
    const float* sbn1_b   = (const float*)d_in[18];
    const float* up2_w    = (const float*)d_in[19];
    const float* up2_b    = (const float*)d_in[20];
    float* out = (float*)d_out;

    float *bufA, *bufB, *first, *second, *msgs, *headbuf;
    cudaGetSymbolAddress((void**)&bufA,    g_bufA);
    cudaGetSymbolAddress((void**)&bufB,    g_bufB);
    cudaGetSymbolAddress((void**)&first,   g_first);
    cudaGetSymbolAddress((void**)&second,  g_second);
    cudaGetSymbolAddress((void**)&msgs,    g_msgs);
    cudaGetSymbolAddress((void**)&headbuf, g_head);

    // conv stack (8 layers), GN+ReLU fused
    conv0_kernel<<<dim3(9, BATCH), 128>>>(x, convs_w0, convs_b0,
                                          gn_gamma, gn_beta, bufA);
    for (int l = 0; l < 7; l++) {
        const float* s = (l % 2 == 0) ? bufA : bufB;
        float*       d = (l % 2 == 0) ? bufB : bufA;
        conv1_kernel<<<dim3(9, BATCH), 128>>>(s,
            convs_w + (size_t)l*576*576*9, convs_b + l*576,
            gn_gamma + (l+1)*576, gn_beta + (l+1)*576, d);
    }
    // h lives in bufB

    // first-order message passing
    mp_kernel<<<dim3(NEDGE, BATCH), 256>>>(bufB, fo_dw_w, fo_dw_b, fo_pw_w, fo_pw_b, msgs);
    gather_kernel<<<(BATCH*C576*HW49 + 255)/256, 256>>>(bufB, msgs, first);
    // second-order (sources = first, base added = h)
    mp_kernel<<<dim3(NEDGE, BATCH), 256>>>(first, so_dw_w, so_dw_b, so_pw_w, so_pw_b, msgs);
    gather_kernel<<<(BATCH*C576*HW49 + 255)/256, 256>>>(bufB, msgs, second);

    // head(h)
    deconv1_kernel<<<dim3(9, BATCH), 256>>>(bufB, up1_w, up1_b, sbn1_g, sbn1_b, headbuf);
    up2_kernel<<<dim3(9, BATCH), 64>>>(headbuf, up2_w, up2_b, out);
    // head(x2)
    deconv1_kernel<<<dim3(9, BATCH), 256>>>(second, up1_w, up1_b, sbn1_g, sbn1_b, headbuf);
    up2_kernel<<<dim3(9, BATCH), 64>>>(headbuf, up2_w, up2_b, out + BATCH*9*784);

    (void)in_sizes; (void)n_in; (void)out_size;
}

// round 3
// speedup vs baseline: 1.0698x; 1.0698x over previous
#include <cuda_runtime.h>

// ---------------- problem constants ----------------
#define BATCH 64
#define C576  576
#define HW49  49
#define NEDGE 24

// ---------------- scratch ----------------
__device__ float g_bufA[BATCH*C576*HW49];
__device__ float g_bufB[BATCH*C576*HW49];
__device__ float g_first[BATCH*C576*HW49];
__device__ float g_second[BATCH*C576*HW49];
__device__ float g_msgs[NEDGE*BATCH*64*HW49];
__device__ float g_head[BATCH*C576*196];

__constant__ int c_esrc[NEDGE] = {1,3, 0,2,4, 1,5, 0,4,6, 1,3,5,7, 2,4,8, 3,7, 4,6,8, 5,7};
__constant__ int c_doff[10]    = {0,2,5,7,10,14,17,19,22,24};

// ---------------- packed fp32x2 helpers (sm_103a FFMA2) ----------------
typedef unsigned long long u64t;
__device__ __forceinline__ u64t pack2(float x, float y) {
    u64t r; asm("mov.b64 %0, {%1, %2};" : "=l"(r) : "f"(x), "f"(y)); return r;
}
__device__ __forceinline__ u64t bcast2(float x) {
    u64t r; asm("mov.b64 %0, {%1, %1};" : "=l"(r) : "f"(x)); return r;
}
__device__ __forceinline__ u64t fma2(u64t a, u64t b, u64t c) {
    u64t d; asm("fma.rn.f32x2 %0, %1, %2, %3;" : "=l"(d) : "l"(a), "l"(b), "l"(c)); return d;
}
__device__ __forceinline__ void unpack2(u64t p, float& x, float& y) {
    asm("mov.b64 {%0, %1}, %2;" : "=f"(x), "=f"(y) : "l"(p));
}

// =====================================================================
// conv0: 3x3 s2 p1, 256->576, 14x14 -> 7x7, fused GN(36)+ReLU, FFMA2
// grid (9 oc-tiles, 64 b), block 128 (112 active)
// =====================================================================
__global__ __launch_bounds__(128) void conv0_kernel(
    const float* __restrict__ x, const float* __restrict__ w,
    const float* __restrict__ bias, const float* __restrict__ gamma,
    const float* __restrict__ beta, float* __restrict__ dst)
{
    const int b   = blockIdx.y;
    const int ocb = blockIdx.x * 64;
    __shared__ float in_s[8][16][16];
    __shared__ __align__(16) float w_s[8][9][66];   // [ic][tap][oc+pad]
    __shared__ float psum[128], psum2[128];
    __shared__ float gmean[4], ginv[4];
    const int tid = threadIdx.x;
    const bool active = tid < 112;
    const int row = tid % 7;
    const int og  = tid / 7;     // 0..15 -> oc base og*4

    u64t accP[2][7];
    if (active) {
#pragma unroll
        for (int op = 0; op < 2; op++) {
            u64t bv = pack2(bias[ocb + og*4 + op*2], bias[ocb + og*4 + op*2 + 1]);
#pragma unroll
            for (int xo = 0; xo < 7; xo++) accP[op][xo] = bv;
        }
    }

    for (int ic0 = 0; ic0 < 256; ic0 += 8) {
        for (int li = tid; li < 8*64*9; li += 128) {
            int ocl = li / 72; int rem = li % 72; int icl = rem / 9; int tap = rem % 9;
            w_s[icl][tap][ocl] = w[((ocb + ocl)*256 + ic0 + icl)*9 + tap];
        }
        for (int li = tid; li < 8*256; li += 128) {
            int icl = li >> 8; int rem = li & 255; int yy = rem >> 4; int xx = rem & 15;
            float v = 0.f;
            if (yy >= 1 && yy <= 14 && xx >= 1 && xx <= 14)
                v = x[((b*256 + ic0 + icl)*14 + yy - 1)*14 + xx - 1];
            in_s[icl][yy][xx] = v;
        }
        __syncthreads();
        if (active) {
#pragma unroll 1
            for (int ic = 0; ic < 8; ic++) {
#pragma unroll
                for (int dy = 0; dy < 3; dy++) {
                    u64t vb[15];
#pragma unroll
                    for (int k = 0; k < 15; k++) vb[k] = bcast2(in_s[ic][2*row + dy][k]);
#pragma unroll
                    for (int op = 0; op < 2; op++) {
                        const float* wrow0 = &w_s[ic][dy*3 + 0][og*4 + op*2];
                        const float* wrow1 = &w_s[ic][dy*3 + 1][og*4 + op*2];
                        const float* wrow2 = &w_s[ic][dy*3 + 2][og*4 + op*2];
                        u64t w0 = *reinterpret_cast<const u64t*>(wrow0);
                        u64t w1 = *reinterpret_cast<const u64t*>(wrow1);
                        u64t w2 = *reinterpret_cast<const u64t*>(wrow2);
#pragma unroll
                        for (int xo = 0; xo < 7; xo++)
                            accP[op][xo] = fma2(w0, vb[2*xo],
                                           fma2(w1, vb[2*xo+1],
                                           fma2(w2, vb[2*xo+2], accP[op][xo])));
                    }
                }
            }
        }
        __syncthreads();
    }

    float accf[4][7];
    float s = 0.f, s2 = 0.f;
    if (active) {
#pragma unroll
        for (int op = 0; op < 2; op++)
#pragma unroll
            for (int xo = 0; xo < 7; xo++) {
                float a, bq; unpack2(accP[op][xo], a, bq);
                accf[op*2][xo] = a; accf[op*2+1][xo] = bq;
                s += a + bq; s2 += a*a + bq*bq;
            }
    }
    psum[tid] = s; psum2[tid] = s2;
    __syncthreads();
    if (active && (tid % 28) == 0) {
        float a = 0.f, a2 = 0.f;
        for (int i = 0; i < 28; i++) { a += psum[tid + i]; a2 += psum2[tid + i]; }
        float m   = a  * (1.f/784.f);
        float var = a2 * (1.f/784.f) - m*m;
        gmean[tid/28] = m;
        ginv[tid/28]  = rsqrtf(var + 1e-5f);
    }
    __syncthreads();
    if (active) {
        int gi = og >> 2;
        float m = gmean[gi], inv = ginv[gi];
#pragma unroll
        for (int oi = 0; oi < 4; oi++) {
            int ch = ocb + og*4 + oi;
            float ga = gamma[ch], be = beta[ch];
#pragma unroll
            for (int xo = 0; xo < 7; xo++) {
                float vv = (accf[oi][xo] - m) * inv * ga + be;
                dst[((b*C576 + ch)*7 + row)*7 + xo] = fmaxf(vv, 0.f);
            }
        }
    }
}

// =====================================================================
// conv1: 3x3 s1 p1, 576->576 on 7x7, fused GN(36)+ReLU, FFMA2
// grid (9, 64), block 128 (112 active)
// =====================================================================
__global__ __launch_bounds__(128) void conv1_kernel(
    const float* __restrict__ src, const float* __restrict__ w,
    const float* __restrict__ bias, const float* __restrict__ gamma,
    const float* __restrict__ beta, float* __restrict__ dst)
{
    const int b   = blockIdx.y;
    const int ocb = blockIdx.x * 64;
    __shared__ float in_s[16][9][9];
    __shared__ __align__(16) float w_s[16][9][66];  // [ic][tap][oc+pad]
    __shared__ float psum[128], psum2[128];
    __shared__ float gmean[4], ginv[4];
    const int tid = threadIdx.x;
    const bool active = tid < 112;
    const int row = tid % 7;
    const int og  = tid / 7;

    u64t accP[2][7];
    if (active) {
#pragma unroll
        for (int op = 0; op < 2; op++) {
            u64t bv = pack2(bias[ocb + og*4 + op*2], bias[ocb + og*4 + op*2 + 1]);
#pragma unroll
            for (int xo = 0; xo < 7; xo++) accP[op][xo] = bv;
        }
    }

    for (int ic0 = 0; ic0 < 576; ic0 += 16) {
        for (int li = tid; li < 16*64*9; li += 128) {
            int ocl = li / 144; int rem = li % 144; int icl = rem / 9; int tap = rem % 9;
            w_s[icl][tap][ocl] = w[((ocb + ocl)*576 + ic0 + icl)*9 + tap];
        }
        for (int li = tid; li < 16*81; li += 128) {
            int icl = li / 81; int rem = li % 81; int yy = rem / 9; int xx = rem % 9;
            float v = 0.f;
            if (yy >= 1 && yy <= 7 && xx >= 1 && xx <= 7)
                v = src[((b*C576 + ic0 + icl)*7 + yy - 1)*7 + xx - 1];
            in_s[icl][yy][xx] = v;
        }
        __syncthreads();
        if (active) {
#pragma unroll 1
            for (int ic = 0; ic < 16; ic++) {
#pragma unroll
                for (int dy = 0; dy < 3; dy++) {
                    u64t vb[9];
#pragma unroll
                    for (int k = 0; k < 9; k++) vb[k] = bcast2(in_s[ic][row + dy][k]);
#pragma unroll
                    for (int op = 0; op < 2; op++) {
                        const float* wrow0 = &w_s[ic][dy*3 + 0][og*4 + op*2];
                        const float* wrow1 = &w_s[ic][dy*3 + 1][og*4 + op*2];
                        const float* wrow2 = &w_s[ic][dy*3 + 2][og*4 + op*2];
                        u64t w0 = *reinterpret_cast<const u64t*>(wrow0);
                        u64t w1 = *reinterpret_cast<const u64t*>(wrow1);
                        u64t w2 = *reinterpret_cast<const u64t*>(wrow2);
#pragma unroll
                        for (int xo = 0; xo < 7; xo++)
                            accP[op][xo] = fma2(w0, vb[xo],
                                           fma2(w1, vb[xo+1],
                                           fma2(w2, vb[xo+2], accP[op][xo])));
                    }
                }
            }
        }
        __syncthreads();
    }

    float accf[4][7];
    float s = 0.f, s2 = 0.f;
    if (active) {
#pragma unroll
        for (int op = 0; op < 2; op++)
#pragma unroll
            for (int xo = 0; xo < 7; xo++) {
                float a, bq; unpack2(accP[op][xo], a, bq);
                accf[op*2][xo] = a; accf[op*2+1][xo] = bq;
                s += a + bq; s2 += a*a + bq*bq;
            }
    }
    psum[tid] = s; psum2[tid] = s2;
    __syncthreads();
    if (active && (tid % 28) == 0) {
        float a = 0.f, a2 = 0.f;
        for (int i = 0; i < 28; i++) { a += psum[tid + i]; a2 += psum2[tid + i]; }
        float m   = a  * (1.f/784.f);
        float var = a2 * (1.f/784.f) - m*m;
        gmean[tid/28] = m;
        ginv[tid/28]  = rsqrtf(var + 1e-5f);
    }
    __syncthreads();
    if (active) {
        int gi = og >> 2;
        float m = gmean[gi], inv = ginv[gi];
#pragma unroll
        for (int oi = 0; oi < 4; oi++) {
            int ch = ocb + og*4 + oi;
            float ga = gamma[ch], be = beta[ch];
#pragma unroll
            for (int xo = 0; xo < 7; xo++) {
                float vv = (accf[oi][xo] - m) * inv * ga + be;
                dst[((b*C576 + ch)*7 + row)*7 + xo] = fmaxf(vv, 0.f);
            }
        }
    }
}

// =====================================================================
// message passing: per-edge depthwise 5x5 (pad2) + pointwise 64x64
// =====================================================================
__global__ __launch_bounds__(256) void mp_kernel(
    const float* __restrict__ src, const float* __restrict__ dw_w,
    const float* __restrict__ dw_b, const float* __restrict__ pw_w,
    const float* __restrict__ pw_b, float* __restrict__ msgs)
{
    const int e = blockIdx.x, b = blockIdx.y;
    const int sg = c_esrc[e];
    __shared__ float in_pad[64][11][11];
    __shared__ float t_s[64][49];
    const int tid = threadIdx.x;

    for (int li = tid; li < 64*121; li += 256) {
        int c = li / 121; int rem = li % 121; int yy = rem / 11; int xx = rem % 11;
        float v = 0.f;
        if (yy >= 2 && yy <= 8 && xx >= 2 && xx <= 8)
            v = src[((b*C576 + sg*64 + c)*7 + yy - 2)*7 + xx - 2];
        in_pad[c][yy][xx] = v;
    }
    __syncthreads();

    for (int idx = tid; idx < 64*49; idx += 256) {
        int c = idx / 49, p = idx % 49, y = p / 7, xx = p % 7;
        float acc = dw_b[e*64 + c];
        const float* wp = dw_w + (e*64 + c)*25;
#pragma unroll
        for (int ky = 0; ky < 5; ky++)
#pragma unroll
            for (int kx = 0; kx < 5; kx++)
                acc = fmaf(in_pad[c][y + ky][xx + kx], wp[ky*5 + kx], acc);
        t_s[c][p] = acc;
    }
    __syncthreads();

    for (int idx = tid; idx < 64*49; idx += 256) {
        int o = idx / 49, p = idx % 49;
        float acc = pw_b[e*64 + o];
        const float* wp = pw_w + (e*64 + o)*64;
#pragma unroll 8
        for (int c = 0; c < 64; c++)
            acc = fmaf(wp[c], t_s[c][p], acc);
        msgs[((e*BATCH + b)*64 + o)*49 + p] = acc;
    }
}

// =====================================================================
// segment-sum gather (deterministic ordered sum)
// =====================================================================
__global__ __launch_bounds__(256) void gather_kernel(
    const float* __restrict__ base, const float* __restrict__ msgs,
    float* __restrict__ out)
{
    int i = blockIdx.x * blockDim.x + threadIdx.x;
    if (i >= BATCH*C576*HW49) return;
    int b = i / (C576*HW49); int rem = i % (C576*HW49);
    int ch = rem / 49; int p = rem % 49;
    int g = ch >> 6; int o = ch & 63;
    float v = base[i];
    int e1 = c_doff[g + 1];
    for (int e = c_doff[g]; e < e1; e++)
        v += msgs[((e*BATCH + b)*64 + o)*49 + p];
    out[i] = v;
}

// =====================================================================
// deconv1 (ConvTranspose k4 s2 p1, groups=9, 64->64, 7->14) + GN + ReLU
// =====================================================================
__global__ __launch_bounds__(256) void deconv1_kernel(
    const float* __restrict__ src, const float* __restrict__ w,
    const float* __restrict__ bias, const float* __restrict__ gamma,
    const float* __restrict__ beta, float* __restrict__ dst)
{
    const int g = blockIdx.x, b = blockIdx.y;
    __shared__ float in_s[64*49];
    __shared__ float red[256], red2[256];
    __shared__ float s_stats[2];
    const int tid = threadIdx.x;

    for (int li = tid; li < 64*49; li += 256)
        in_s[li] = src[(b*C576 + g*64)*49 + li];
    __syncthreads();

    const bool active = tid < 224;
    const int ocg = tid / 14;
    const int row = tid % 14;
    float acc[4][14];
    if (active) {
#pragma unroll
        for (int oi = 0; oi < 4; oi++)
#pragma unroll
            for (int ox = 0; ox < 14; ox++) acc[oi][ox] = 0.f;

        const int kp = (row + 1) & 1;
#pragma unroll 1
        for (int ic = 0; ic < 64; ic++) {
            const float* wbase = w + (((g*64 + ic)*64) + ocg*4) * 16;
#pragma unroll
            for (int t = 0; t < 2; t++) {
                int ky = kp + 2*t;
                int iy = (row + 1 - ky) >> 1;
                if (iy < 0 || iy >= 7) continue;
                float v[7];
#pragma unroll
                for (int j = 0; j < 7; j++) v[j] = in_s[ic*49 + iy*7 + j];
#pragma unroll
                for (int kx = 0; kx < 4; kx++) {
                    float w4[4];
#pragma unroll
                    for (int oi = 0; oi < 4; oi++)
                        w4[oi] = __ldg(wbase + oi*16 + ky*4 + kx);
#pragma unroll
                    for (int j = 0; j < 7; j++) {
                        const int ox = 2*j - 1 + kx;
                        if (ox < 0 || ox > 13) continue;
#pragma unroll
                        for (int oi = 0; oi < 4; oi++)
                            acc[oi][ox] = fmaf(w4[oi], v[j], acc[oi][ox]);
                    }
                }
            }
        }
    }

    float lsum = 0.f, lsum2 = 0.f;
    if (active) {
#pragma unroll
        for (int oi = 0; oi < 4; oi++) {
            float bv = bias[g*64 + ocg*4 + oi];
#pragma unroll
            for (int ox = 0; ox < 14; ox++) {
                float val = acc[oi][ox] + bv;
                acc[oi][ox] = val;
                lsum += val; lsum2 += val*val;
            }
        }
    }
    red[tid] = lsum; red2[tid] = lsum2;
    __syncthreads();
    for (int s = 128; s > 0; s >>= 1) {
        if (tid < s) { red[tid] += red[tid + s]; red2[tid] += red2[tid + s]; }
        __syncthreads();
    }
    if (tid == 0) {
        float m   = red[0]  * (1.f/12544.f);
        float var = red2[0] * (1.f/12544.f) - m*m;
        s_stats[0] = m;
        s_stats[1] = rsqrtf(var + 1e-5f);
    }
    __syncthreads();
    if (active) {
        float m = s_stats[0], inv = s_stats[1];
#pragma unroll
        for (int oi = 0; oi < 4; oi++) {
            int ch = g*64 + ocg*4 + oi;
            float ga = gamma[ch], be = beta[ch];
#pragma unroll
            for (int ox = 0; ox < 14; ox++) {
                float val = (acc[oi][ox] - m) * inv * ga + be;
                dst[(b*C576 + ch)*196 + row*14 + ox] = fmaxf(val, 0.f);
            }
        }
    }
}

// =====================================================================
// up2 (ConvTranspose k4 s2 p1, groups=9, 64->1, 14->28)
// =====================================================================
__global__ __launch_bounds__(64) void up2_kernel(
    const float* __restrict__ src, const float* __restrict__ w,
    const float* __restrict__ bias, float* __restrict__ out)
{
    const int g = blockIdx.x, b = blockIdx.y;
    const int tid = threadIdx.x;
    if (tid >= 49) return;
    const int r2 = tid / 7, c2 = tid % 7;
    const int iy0 = 2*r2 - 1, ix0 = 2*c2 - 1;

    const int TK[4][2] = {{1,3},{0,2},{1,3},{0,2}};
    const int TR[4][2] = {{1,0},{2,1},{2,1},{3,2}};

    float acc[4][4];
#pragma unroll
    for (int a = 0; a < 4; a++)
#pragma unroll
        for (int c = 0; c < 4; c++) acc[a][c] = 0.f;

#pragma unroll 1
    for (int ic = 0; ic < 64; ic++) {
        const float* ib = src + (b*C576 + g*64 + ic)*196;
        float vin[4][4];
#pragma unroll
        for (int a = 0; a < 4; a++) {
            int iy = iy0 + a;
#pragma unroll
            for (int c = 0; c < 4; c++) {
                int ix = ix0 + c;
                vin[a][c] = (iy >= 0 && iy < 14 && ix >= 0 && ix < 14)
                          ? __ldg(ib + iy*14 + ix) : 0.f;
            }
        }
        float w16[16];
#pragma unroll
        for (int t = 0; t < 16; t++) w16[t] = __ldg(w + (g*64 + ic)*16 + t);

#pragma unroll
        for (int dy = 0; dy < 4; dy++)
#pragma unroll
            for (int dx = 0; dx < 4; dx++)
#pragma unroll
                for (int i = 0; i < 2; i++)
#pragma unroll
                    for (int j = 0; j < 2; j++)
                        acc[dy][dx] = fmaf(w16[TK[dy][i]*4 + TK[dx][j]],
                                           vin[TR[dy][i]][TR[dx][j]], acc[dy][dx]);
    }
    const float bz = bias[g];
#pragma unroll
    for (int dy = 0; dy < 4; dy++)
#pragma unroll
        for (int dx = 0; dx < 4; dx++)
            out[(b*9 + g)*784 + (4*r2 + dy)*28 + (4*c2 + dx)] = acc[dy][dx] + bz;
}

// =====================================================================
// host launch
// =====================================================================
extern "C" void kernel_launch(void* const* d_in, const int* in_sizes, int n_in,
                              void* d_out, int out_size)
{
    const float* x        = (const float*)d_in[0];
    const float* convs_w0 = (const float*)d_in[1];
    const float* convs_b0 = (const float*)d_in[2];
    const float* convs_w  = (const float*)d_in[3];
    const float* convs_b  = (const float*)d_in[4];
    const float* gn_gamma = (const float*)d_in[5];
    const float* gn_beta  = (const float*)d_in[6];
    const float* fo_dw_w  = (const float*)d_in[7];
    const float* fo_dw_b  = (const float*)d_in[8];
    const float* fo_pw_w  = (const float*)d_in[9];
    const float* fo_pw_b  = (const float*)d_in[10];
    const float* so_dw_w  = (const float*)d_in[11];
    const float* so_dw_b  = (const float*)d_in[12];
    const float* so_pw_w  = (const float*)d_in[13];
    const float* so_pw_b  = (const float*)d_in[14];
    const float* up1_w    = (const float*)d_in[15];
    const float* up1_b    = (const float*)d_in[16];
    const float* sbn1_g   = (const float*)d_in[17];
    const float* sbn1_b   = (const float*)d_in[18];
    const float* up2_w    = (const float*)d_in[19];
    const float* up2_b    = (const float*)d_in[20];
    float* out = (float*)d_out;

    float *bufA, *bufB, *first, *second, *msgs, *headbuf;
    cudaGetSymbolAddress((void**)&bufA,    g_bufA);
    cudaGetSymbolAddress((void**)&bufB,    g_bufB);
    cudaGetSymbolAddress((void**)&first,   g_first);
    cudaGetSymbolAddress((void**)&second,  g_second);
    cudaGetSymbolAddress((void**)&msgs,    g_msgs);
    cudaGetSymbolAddress((void**)&headbuf, g_head);

    conv0_kernel<<<dim3(9, BATCH), 128>>>(x, convs_w0, convs_b0,
                                          gn_gamma, gn_beta, bufA);
    for (int l = 0; l < 7; l++) {
        const float* s = (l % 2 == 0) ? bufA : bufB;
        float*       d = (l % 2 == 0) ? bufB : bufA;
        conv1_kernel<<<dim3(9, BATCH), 128>>>(s,
            convs_w + (size_t)l*576*576*9, convs_b + l*576,
            gn_gamma + (l+1)*576, gn_beta + (l+1)*576, d);
    }

    mp_kernel<<<dim3(NEDGE, BATCH), 256>>>(bufB, fo_dw_w, fo_dw_b, fo_pw_w, fo_pw_b, msgs);
    gather_kernel<<<(BATCH*C576*HW49 + 255)/256, 256>>>(bufB, msgs, first);
    mp_kernel<<<dim3(NEDGE, BATCH), 256>>>(first, so_dw_w, so_dw_b, so_pw_w, so_pw_b, msgs);
    gather_kernel<<<(BATCH*C576*HW49 + 255)/256, 256>>>(bufB, msgs, second);

    deconv1_kernel<<<dim3(9, BATCH), 256>>>(bufB, up1_w, up1_b, sbn1_g, sbn1_b, headbuf);
    up2_kernel<<<dim3(9, BATCH), 64>>>(headbuf, up2_w, up2_b, out);
    deconv1_kernel<<<dim3(9, BATCH), 256>>>(second, up1_w, up1_b, sbn1_g, sbn1_b, headbuf);
    up2_kernel<<<dim3(9, BATCH), 64>>>(headbuf, up2_w, up2_b, out + BATCH*9*784);

    (void)in_sizes; (void)n_in; (void)out_size;
}

// round 4
// speedup vs baseline: 1.1491x; 1.0741x over previous
#include <cuda_runtime.h>

// ---------------- problem constants ----------------
#define BATCH 64
#define C576  576
#define HW49  49
#define NEDGE 24

// ---------------- scratch ----------------
__device__ float g_bufA[BATCH*C576*HW49];
__device__ float g_bufB[BATCH*C576*HW49];
__device__ float g_first[BATCH*C576*HW49];
__device__ float g_second[BATCH*C576*HW49];
__device__ float g_msgs[NEDGE*BATCH*64*HW49];
__device__ float g_head[BATCH*C576*196];

__constant__ int c_esrc[NEDGE] = {1,3, 0,2,4, 1,5, 0,4,6, 1,3,5,7, 2,4,8, 3,7, 4,6,8, 5,7};
__constant__ int c_doff[10]    = {0,2,5,7,10,14,17,19,22,24};

// ---------------- packed fp32x2 helpers ----------------
typedef unsigned long long u64t;
__device__ __forceinline__ u64t pack2(float x, float y) {
    u64t r; asm("mov.b64 %0, {%1, %2};" : "=l"(r) : "f"(x), "f"(y)); return r;
}
__device__ __forceinline__ u64t fma2(u64t a, u64t b, u64t c) {
    u64t d; asm("fma.rn.f32x2 %0, %1, %2, %3;" : "=l"(d) : "l"(a), "l"(b), "l"(c)); return d;
}
__device__ __forceinline__ void unpack2(u64t p, float& x, float& y) {
    asm("mov.b64 {%0, %1}, %2;" : "=f"(x), "=f"(y) : "l"(p));
}

// =====================================================================
// conv1: 3x3 s1 p1, 576->576 on 7x7, fused GN(36)+ReLU
// 2 batches per block, dup-input broadcast LDS.64, FFMA2.
// grid (9 octile, 32 bpair), block 224 (all active)
// smem layout (dynamic):
//   in_d  : float2 [2][16][9][10]   = 23040 B
//   w_s   : float  [16][9][66]      = 38016 B
//   psum  : float [224], psum2 [224], gstat [16]
// =====================================================================
#define C1_SMEM (23040 + 38016 + 224*4*2 + 64)
__global__ __launch_bounds__(224) void conv1_kernel(
    const float* __restrict__ src, const float* __restrict__ w,
    const float* __restrict__ bias, const float* __restrict__ gamma,
    const float* __restrict__ beta, float* __restrict__ dst)
{
    extern __shared__ char sm_raw[];
    float2* in_d  = (float2*)sm_raw;                          // [2][16][9][10]
    float*  w_s   = (float*)(sm_raw + 23040);                 // [16][9][66]
    float*  psum  = (float*)(sm_raw + 23040 + 38016);
    float*  psum2 = psum + 224;
    float*  gstat = psum2 + 224;                              // mean[8], inv[8]

    const int b0  = blockIdx.y * 2;
    const int ocb = blockIdx.x * 64;
    const int tid = threadIdx.x;
    const int bh  = tid / 112;
    const int t   = tid % 112;
    const int row = t % 7;
    const int og  = t / 7;        // 0..15
    const int b   = b0 + bh;

    u64t accP[2][7];
#pragma unroll
    for (int op = 0; op < 2; op++) {
        u64t bv = pack2(bias[ocb + og*4 + op*2], bias[ocb + og*4 + op*2 + 1]);
#pragma unroll
        for (int xo = 0; xo < 7; xo++) accP[op][xo] = bv;
    }

    for (int ic0 = 0; ic0 < 576; ic0 += 16) {
        for (int li = tid; li < 16*64*9; li += 224) {
            int ocl = li / 144; int rem = li % 144; int icl = rem / 9; int tap = rem % 9;
            w_s[(icl*9 + tap)*66 + ocl] = w[((ocb + ocl)*576 + ic0 + icl)*9 + tap];
        }
        for (int li = tid; li < 2*16*81; li += 224) {
            int bb = li / 1296; int rem = li % 1296;
            int icl = rem / 81; int r2 = rem % 81; int yy = r2 / 9; int xx = r2 % 9;
            float v = 0.f;
            if (yy >= 1 && yy <= 7 && xx >= 1 && xx <= 7)
                v = src[((b0 + bb)*C576 + ic0 + icl)*49 + (yy - 1)*7 + xx - 1];
            in_d[((bb*16 + icl)*9 + yy)*10 + xx] = make_float2(v, v);
        }
        __syncthreads();
#pragma unroll 1
        for (int ic = 0; ic < 16; ic++) {
#pragma unroll
            for (int dy = 0; dy < 3; dy++) {
                const u64t* vrow = (const u64t*)&in_d[((bh*16 + ic)*9 + row + dy)*10];
                u64t vb[9];
#pragma unroll
                for (int k = 0; k < 9; k++) vb[k] = vrow[k];
#pragma unroll
                for (int op = 0; op < 2; op++) {
                    const float* wr = &w_s[(ic*9 + dy*3)*66 + og*4 + op*2];
                    u64t w0 = *(const u64t*)(wr);
                    u64t w1 = *(const u64t*)(wr + 66);
                    u64t w2 = *(const u64t*)(wr + 132);
#pragma unroll
                    for (int xo = 0; xo < 7; xo++)
                        accP[op][xo] = fma2(w0, vb[xo],
                                       fma2(w1, vb[xo+1],
                                       fma2(w2, vb[xo+2], accP[op][xo])));
                }
            }
        }
        __syncthreads();
    }

    // GN(36) epilogue: chunk c = tid/28 owns one (batch-half, 16ch) group
    float accf[4][7];
    float s = 0.f, s2 = 0.f;
#pragma unroll
    for (int op = 0; op < 2; op++)
#pragma unroll
        for (int xo = 0; xo < 7; xo++) {
            float a, q; unpack2(accP[op][xo], a, q);
            accf[op*2][xo] = a; accf[op*2+1][xo] = q;
            s += a + q; s2 += a*a + q*q;
        }
    psum[tid] = s; psum2[tid] = s2;
    __syncthreads();
    if ((tid % 28) == 0) {
        float a = 0.f, a2 = 0.f;
        for (int i = 0; i < 28; i++) { a += psum[tid + i]; a2 += psum2[tid + i]; }
        float m   = a  * (1.f/784.f);
        float var = a2 * (1.f/784.f) - m*m;
        gstat[tid/28]     = m;
        gstat[8 + tid/28] = rsqrtf(var + 1e-5f);
    }
    __syncthreads();
    {
        int c = tid / 28;
        float m = gstat[c], inv = gstat[8 + c];
#pragma unroll
        for (int oi = 0; oi < 4; oi++) {
            int ch = ocb + og*4 + oi;
            float ga = gamma[ch], be = beta[ch];
#pragma unroll
            for (int xo = 0; xo < 7; xo++) {
                float vv = (accf[oi][xo] - m) * inv * ga + be;
                dst[((b*C576 + ch)*7 + row)*7 + xo] = fmaxf(vv, 0.f);
            }
        }
    }
}

// =====================================================================
// conv0: 3x3 s2 p1, 256->576, 14x14 -> 7x7, fused GN(36)+ReLU
// same scheme: 2 batches/block, dup input. grid (9, 32), block 224.
//   in_d : float2 [2][8][16][17] = 34816 B
//   w_s  : float  [8][9][66]     = 19008 B
// =====================================================================
#define C0_SMEM (34816 + 19008 + 224*4*2 + 64)
__global__ __launch_bounds__(224) void conv0_kernel(
    const float* __restrict__ x, const float* __restrict__ w,
    const float* __restrict__ bias, const float* __restrict__ gamma,
    const float* __restrict__ beta, float* __restrict__ dst)
{
    extern __shared__ char sm_raw[];
    float2* in_d  = (float2*)sm_raw;                          // [2][8][16][17]
    float*  w_s   = (float*)(sm_raw + 34816);                 // [8][9][66]
    float*  psum  = (float*)(sm_raw + 34816 + 19008);
    float*  psum2 = psum + 224;
    float*  gstat = psum2 + 224;

    const int b0  = blockIdx.y * 2;
    const int ocb = blockIdx.x * 64;
    const int tid = threadIdx.x;
    const int bh  = tid / 112;
    const int t   = tid % 112;
    const int row = t % 7;
    const int og  = t / 7;
    const int b   = b0 + bh;

    u64t accP[2][7];
#pragma unroll
    for (int op = 0; op < 2; op++) {
        u64t bv = pack2(bias[ocb + og*4 + op*2], bias[ocb + og*4 + op*2 + 1]);
#pragma unroll
        for (int xo = 0; xo < 7; xo++) accP[op][xo] = bv;
    }

    for (int ic0 = 0; ic0 < 256; ic0 += 8) {
        for (int li = tid; li < 8*64*9; li += 224) {
            int ocl = li / 72; int rem = li % 72; int icl = rem / 9; int tap = rem % 9;
            w_s[(icl*9 + tap)*66 + ocl] = w[((ocb + ocl)*256 + ic0 + icl)*9 + tap];
        }
        for (int li = tid; li < 2*8*256; li += 224) {
            int bb = li / 2048; int rem = li % 2048;
            int icl = rem >> 8; int r2 = rem & 255; int yy = r2 >> 4; int xx = r2 & 15;
            float v = 0.f;
            if (yy >= 1 && yy <= 14 && xx >= 1 && xx <= 14)
                v = x[((b0 + bb)*256 + ic0 + icl)*196 + (yy - 1)*14 + xx - 1];
            in_d[((bb*8 + icl)*16 + yy)*17 + xx] = make_float2(v, v);
        }
        __syncthreads();
#pragma unroll 1
        for (int ic = 0; ic < 8; ic++) {
#pragma unroll
            for (int dy = 0; dy < 3; dy++) {
                const u64t* vrow = (const u64t*)&in_d[((bh*8 + ic)*16 + 2*row + dy)*17];
                u64t vb[15];
#pragma unroll
                for (int k = 0; k < 15; k++) vb[k] = vrow[k];
#pragma unroll
                for (int op = 0; op < 2; op++) {
                    const float* wr = &w_s[(ic*9 + dy*3)*66 + og*4 + op*2];
                    u64t w0 = *(const u64t*)(wr);
                    u64t w1 = *(const u64t*)(wr + 66);
                    u64t w2 = *(const u64t*)(wr + 132);
#pragma unroll
                    for (int xo = 0; xo < 7; xo++)
                        accP[op][xo] = fma2(w0, vb[2*xo],
                                       fma2(w1, vb[2*xo+1],
                                       fma2(w2, vb[2*xo+2], accP[op][xo])));
                }
            }
        }
        __syncthreads();
    }

    float accf[4][7];
    float s = 0.f, s2 = 0.f;
#pragma unroll
    for (int op = 0; op < 2; op++)
#pragma unroll
        for (int xo = 0; xo < 7; xo++) {
            float a, q; unpack2(accP[op][xo], a, q);
            accf[op*2][xo] = a; accf[op*2+1][xo] = q;
            s += a + q; s2 += a*a + q*q;
        }
    psum[tid] = s; psum2[tid] = s2;
    __syncthreads();
    if ((tid % 28) == 0) {
        float a = 0.f, a2 = 0.f;
        for (int i = 0; i < 28; i++) { a += psum[tid + i]; a2 += psum2[tid + i]; }
        float m   = a  * (1.f/784.f);
        float var = a2 * (1.f/784.f) - m*m;
        gstat[tid/28]     = m;
        gstat[8 + tid/28] = rsqrtf(var + 1e-5f);
    }
    __syncthreads();
    {
        int c = tid / 28;
        float m = gstat[c], inv = gstat[8 + c];
#pragma unroll
        for (int oi = 0; oi < 4; oi++) {
            int ch = ocb + og*4 + oi;
            float ga = gamma[ch], be = beta[ch];
#pragma unroll
            for (int xo = 0; xo < 7; xo++) {
                float vv = (accf[oi][xo] - m) * inv * ga + be;
                dst[((b*C576 + ch)*7 + row)*7 + xo] = fmaxf(vv, 0.f);
            }
        }
    }
}

// =====================================================================
// message passing: per-edge depthwise 5x5 (pad2) + pointwise 64x64
// =====================================================================
__global__ __launch_bounds__(256) void mp_kernel(
    const float* __restrict__ src, const float* __restrict__ dw_w,
    const float* __restrict__ dw_b, const float* __restrict__ pw_w,
    const float* __restrict__ pw_b, float* __restrict__ msgs)
{
    const int e = blockIdx.x, b = blockIdx.y;
    const int sg = c_esrc[e];
    __shared__ float in_pad[64][11][11];
    __shared__ float t_s[64][49];
    const int tid = threadIdx.x;

    for (int li = tid; li < 64*121; li += 256) {
        int c = li / 121; int rem = li % 121; int yy = rem / 11; int xx = rem % 11;
        float v = 0.f;
        if (yy >= 2 && yy <= 8 && xx >= 2 && xx <= 8)
            v = src[((b*C576 + sg*64 + c)*7 + yy - 2)*7 + xx - 2];
        in_pad[c][yy][xx] = v;
    }
    __syncthreads();

    for (int idx = tid; idx < 64*49; idx += 256) {
        int c = idx / 49, p = idx % 49, y = p / 7, xx = p % 7;
        float acc = dw_b[e*64 + c];
        const float* wp = dw_w + (e*64 + c)*25;
#pragma unroll
        for (int ky = 0; ky < 5; ky++)
#pragma unroll
            for (int kx = 0; kx < 5; kx++)
                acc = fmaf(in_pad[c][y + ky][xx + kx], wp[ky*5 + kx], acc);
        t_s[c][p] = acc;
    }
    __syncthreads();

    for (int idx = tid; idx < 64*49; idx += 256) {
        int o = idx / 49, p = idx % 49;
        float acc = pw_b[e*64 + o];
        const float* wp = pw_w + (e*64 + o)*64;
#pragma unroll 8
        for (int c = 0; c < 64; c++)
            acc = fmaf(wp[c], t_s[c][p], acc);
        msgs[((e*BATCH + b)*64 + o)*49 + p] = acc;
    }
}

// =====================================================================
// segment-sum gather (deterministic ordered sum)
// =====================================================================
__global__ __launch_bounds__(256) void gather_kernel(
    const float* __restrict__ base, const float* __restrict__ msgs,
    float* __restrict__ out)
{
    int i = blockIdx.x * blockDim.x + threadIdx.x;
    if (i >= BATCH*C576*HW49) return;
    int b = i / (C576*HW49); int rem = i % (C576*HW49);
    int ch = rem / 49; int p = rem % 49;
    int g = ch >> 6; int o = ch & 63;
    float v = base[i];
    int e1 = c_doff[g + 1];
    for (int e = c_doff[g]; e < e1; e++)
        v += msgs[((e*BATCH + b)*64 + o)*49 + p];
    out[i] = v;
}

// =====================================================================
// deconv1 (ConvTranspose k4 s2 p1, groups=9, 64->64, 7->14) + GN + ReLU
// =====================================================================
__global__ __launch_bounds__(256) void deconv1_kernel(
    const float* __restrict__ src, const float* __restrict__ w,
    const float* __restrict__ bias, const float* __restrict__ gamma,
    const float* __restrict__ beta, float* __restrict__ dst)
{
    const int g = blockIdx.x, b = blockIdx.y;
    __shared__ float in_s[64*49];
    __shared__ float red[256], red2[256];
    __shared__ float s_stats[2];
    const int tid = threadIdx.x;

    for (int li = tid; li < 64*49; li += 256)
        in_s[li] = src[(b*C576 + g*64)*49 + li];
    __syncthreads();

    const bool active = tid < 224;
    const int ocg = tid / 14;
    const int row = tid % 14;
    float acc[4][14];
    if (active) {
#pragma unroll
        for (int oi = 0; oi < 4; oi++)
#pragma unroll
            for (int ox = 0; ox < 14; ox++) acc[oi][ox] = 0.f;

        const int kp = (row + 1) & 1;
#pragma unroll 1
        for (int ic = 0; ic < 64; ic++) {
            const float* wbase = w + (((g*64 + ic)*64) + ocg*4) * 16;
#pragma unroll
            for (int t = 0; t < 2; t++) {
                int ky = kp + 2*t;
                int iy = (row + 1 - ky) >> 1;
                if (iy < 0 || iy >= 7) continue;
                float v[7];
#pragma unroll
                for (int j = 0; j < 7; j++) v[j] = in_s[ic*49 + iy*7 + j];
#pragma unroll
                for (int kx = 0; kx < 4; kx++) {
                    float w4[4];
#pragma unroll
                    for (int oi = 0; oi < 4; oi++)
                        w4[oi] = __ldg(wbase + oi*16 + ky*4 + kx);
#pragma unroll
                    for (int j = 0; j < 7; j++) {
                        const int ox = 2*j - 1 + kx;
                        if (ox < 0 || ox > 13) continue;
#pragma unroll
                        for (int oi = 0; oi < 4; oi++)
                            acc[oi][ox] = fmaf(w4[oi], v[j], acc[oi][ox]);
                    }
                }
            }
        }
    }

    float lsum = 0.f, lsum2 = 0.f;
    if (active) {
#pragma unroll
        for (int oi = 0; oi < 4; oi++) {
            float bv = bias[g*64 + ocg*4 + oi];
#pragma unroll
            for (int ox = 0; ox < 14; ox++) {
                float val = acc[oi][ox] + bv;
                acc[oi][ox] = val;
                lsum += val; lsum2 += val*val;
            }
        }
    }
    red[tid] = lsum; red2[tid] = lsum2;
    __syncthreads();
    for (int s = 128; s > 0; s >>= 1) {
        if (tid < s) { red[tid] += red[tid + s]; red2[tid] += red2[tid + s]; }
        __syncthreads();
    }
    if (tid == 0) {
        float m   = red[0]  * (1.f/12544.f);
        float var = red2[0] * (1.f/12544.f) - m*m;
        s_stats[0] = m;
        s_stats[1] = rsqrtf(var + 1e-5f);
    }
    __syncthreads();
    if (active) {
        float m = s_stats[0], inv = s_stats[1];
#pragma unroll
        for (int oi = 0; oi < 4; oi++) {
            int ch = g*64 + ocg*4 + oi;
            float ga = gamma[ch], be = beta[ch];
#pragma unroll
            for (int ox = 0; ox < 14; ox++) {
                float val = (acc[oi][ox] - m) * inv * ga + be;
                dst[(b*C576 + ch)*196 + row*14 + ox] = fmaxf(val, 0.f);
            }
        }
    }
}

// =====================================================================
// up2 (ConvTranspose k4 s2 p1, groups=9, 64->1, 14->28)
// =====================================================================
__global__ __launch_bounds__(64) void up2_kernel(
    const float* __restrict__ src, const float* __restrict__ w,
    const float* __restrict__ bias, float* __restrict__ out)
{
    const int g = blockIdx.x, b = blockIdx.y;
    const int tid = threadIdx.x;
    if (tid >= 49) return;
    const int r2 = tid / 7, c2 = tid % 7;
    const int iy0 = 2*r2 - 1, ix0 = 2*c2 - 1;

    const int TK[4][2] = {{1,3},{0,2},{1,3},{0,2}};
    const int TR[4][2] = {{1,0},{2,1},{2,1},{3,2}};

    float acc[4][4];
#pragma unroll
    for (int a = 0; a < 4; a++)
#pragma unroll
        for (int c = 0; c < 4; c++) acc[a][c] = 0.f;

#pragma unroll 1
    for (int ic = 0; ic < 64; ic++) {
        const float* ib = src + (b*C576 + g*64 + ic)*196;
        float vin[4][4];
#pragma unroll
        for (int a = 0; a < 4; a++) {
            int iy = iy0 + a;
#pragma unroll
            for (int c = 0; c < 4; c++) {
                int ix = ix0 + c;
                vin[a][c] = (iy >= 0 && iy < 14 && ix >= 0 && ix < 14)
                          ? __ldg(ib + iy*14 + ix) : 0.f;
            }
        }
        float w16[16];
#pragma unroll
        for (int t = 0; t < 16; t++) w16[t] = __ldg(w + (g*64 + ic)*16 + t);

#pragma unroll
        for (int dy = 0; dy < 4; dy++)
#pragma unroll
            for (int dx = 0; dx < 4; dx++)
#pragma unroll
                for (int i = 0; i < 2; i++)
#pragma unroll
                    for (int j = 0; j < 2; j++)
                        acc[dy][dx] = fmaf(w16[TK[dy][i]*4 + TK[dx][j]],
                                           vin[TR[dy][i]][TR[dx][j]], acc[dy][dx]);
    }
    const float bz = bias[g];
#pragma unroll
    for (int dy = 0; dy < 4; dy++)
#pragma unroll
        for (int dx = 0; dx < 4; dx++)
            out[(b*9 + g)*784 + (4*r2 + dy)*28 + (4*c2 + dx)] = acc[dy][dx] + bz;
}

// =====================================================================
// host launch
// =====================================================================
extern "C" void kernel_launch(void* const* d_in, const int* in_sizes, int n_in,
                              void* d_out, int out_size)
{
    const float* x        = (const float*)d_in[0];
    const float* convs_w0 = (const float*)d_in[1];
    const float* convs_b0 = (const float*)d_in[2];
    const float* convs_w  = (const float*)d_in[3];
    const float* convs_b  = (const float*)d_in[4];
    const float* gn_gamma = (const float*)d_in[5];
    const float* gn_beta  = (const float*)d_in[6];
    const float* fo_dw_w  = (const float*)d_in[7];
    const float* fo_dw_b  = (const float*)d_in[8];
    const float* fo_pw_w  = (const float*)d_in[9];
    const float* fo_pw_b  = (const float*)d_in[10];
    const float* so_dw_w  = (const float*)d_in[11];
    const float* so_dw_b  = (const float*)d_in[12];
    const float* so_pw_w  = (const float*)d_in[13];
    const float* so_pw_b  = (const float*)d_in[14];
    const float* up1_w    = (const float*)d_in[15];
    const float* up1_b    = (const float*)d_in[16];
    const float* sbn1_g   = (const float*)d_in[17];
    const float* sbn1_b   = (const float*)d_in[18];
    const float* up2_w    = (const float*)d_in[19];
    const float* up2_b    = (const float*)d_in[20];
    float* out = (float*)d_out;

    float *bufA, *bufB, *first, *second, *msgs, *headbuf;
    cudaGetSymbolAddress((void**)&bufA,    g_bufA);
    cudaGetSymbolAddress((void**)&bufB,    g_bufB);
    cudaGetSymbolAddress((void**)&first,   g_first);
    cudaGetSymbolAddress((void**)&second,  g_second);
    cudaGetSymbolAddress((void**)&msgs,    g_msgs);
    cudaGetSymbolAddress((void**)&headbuf, g_head);

    cudaFuncSetAttribute(conv0_kernel, cudaFuncAttributeMaxDynamicSharedMemorySize, C0_SMEM);
    cudaFuncSetAttribute(conv1_kernel, cudaFuncAttributeMaxDynamicSharedMemorySize, C1_SMEM);

    conv0_kernel<<<dim3(9, 32), 224, C0_SMEM>>>(x, convs_w0, convs_b0,
                                                gn_gamma, gn_beta, bufA);
    for (int l = 0; l < 7; l++) {
        const float* s = (l % 2 == 0) ? bufA : bufB;
        float*       d = (l % 2 == 0) ? bufB : bufA;
        conv1_kernel<<<dim3(9, 32), 224, C1_SMEM>>>(s,
            convs_w + (size_t)l*576*576*9, convs_b + l*576,
            gn_gamma + (l+1)*576, gn_beta + (l+1)*576, d);
    }

    mp_kernel<<<dim3(NEDGE, BATCH), 256>>>(bufB, fo_dw_w, fo_dw_b, fo_pw_w, fo_pw_b, msgs);
    gather_kernel<<<(BATCH*C576*HW49 + 255)/256, 256>>>(bufB, msgs, first);
    mp_kernel<<<dim3(NEDGE, BATCH), 256>>>(first, so_dw_w, so_dw_b, so_pw_w, so_pw_b, msgs);
    gather_kernel<<<(BATCH*C576*HW49 + 255)/256, 256>>>(bufB, msgs, second);

    deconv1_kernel<<<dim3(9, BATCH), 256>>>(bufB, up1_w, up1_b, sbn1_g, sbn1_b, headbuf);
    up2_kernel<<<dim3(9, BATCH), 64>>>(headbuf, up2_w, up2_b, out);
    deconv1_kernel<<<dim3(9, BATCH), 256>>>(second, up1_w, up1_b, sbn1_g, sbn1_b, headbuf);
    up2_kernel<<<dim3(9, BATCH), 64>>>(headbuf, up2_w, up2_b, out + BATCH*9*784);

    (void)in_sizes; (void)n_in; (void)out_size;
}